// round 1
// baseline (speedup 1.0000x reference)
#include <cuda_runtime.h>
#include <cstdint>

#define B_SZ   512
#define PX     512
#define PH     1024
#define PL     4
#define PVT    512
#define PET    256
#define NG     4096      // 4 gates * PH, rows of gate weight per layer
#define HID    4096      // PL * PH
#define IN_DIM 2560

// Scratch (no allocations allowed): partial/full gate pre-activations + hidden
__device__ float g_Gp[PL * B_SZ * NG];      // 33.5 MB
__device__ float g_hidden[B_SZ * HID];      // 8.4 MB

__device__ __forceinline__ float f2tf32(float x) {
    uint32_t r;
    asm("cvt.rna.tf32.f32 %0, %1;" : "=r"(r) : "f"(x));
    return __uint_as_float(r);
}

__device__ __forceinline__ void mma_tf32(float (&d)[4], const uint32_t (&a)[4],
                                         uint32_t b0, uint32_t b1) {
    asm volatile(
        "mma.sync.aligned.m16n8k8.row.col.f32.tf32.tf32.f32 "
        "{%0,%1,%2,%3}, {%4,%5,%6,%7}, {%8,%9}, {%0,%1,%2,%3};\n"
        : "+f"(d[0]), "+f"(d[1]), "+f"(d[2]), "+f"(d[3])
        : "r"(a[0]), "r"(a[1]), "r"(a[2]), "r"(a[3]), "r"(b0), "r"(b1));
}

// MODE 0: partial gates for all layers (grid.z = layer).
//         A = [x | h_prev[layer]] (K = 1536), B = Wg[layer][:, 0:1536], +bias bg.
//         D = g_Gp[layer].
// MODE 1: sequential tail for `layer`.
//         A = g_hidden[:, (layer-1)*PH : layer*PH] (K = 1024),
//         B = Wg[layer][:, 1536:2560], D = g_Gp[layer] (accumulate in-place).
// MODE 2: heads. A = g_hidden (K = 4096), B rows 0:512 = W_y, 512:768 = W_E,
//         bias b_y/b_E, write split output layout into d_out.
template<int MODE>
__global__ void __launch_bounds__(256)
gemm_tf32(const float* __restrict__ x,
          const float* __restrict__ h_prev,
          const float* __restrict__ Wg,
          const float* __restrict__ bg,
          const float* __restrict__ W_y, const float* __restrict__ b_y,
          const float* __restrict__ W_E, const float* __restrict__ b_E,
          float* __restrict__ d_out,
          int layer)
{
    constexpr int BM = 128, BN = 128, BK = 32;
    __shared__ float As[BM][BK + 1];
    __shared__ float Bs[BN][BK + 1];

    const int tid = threadIdx.x;
    const int bm  = blockIdx.y * BM;
    const int bn  = blockIdx.x * BN;
    const int lz  = (MODE == 0) ? blockIdx.z : layer;

    int Ktot;
    if (MODE == 0)      Ktot = PX + PH;   // 1536
    else if (MODE == 1) Ktot = PH;        // 1024
    else                Ktot = HID;       // 4096

    // loader indexing: 256 threads, float4 per access; 128x32 tile = 1024 float4
    const int lr = tid >> 3;          // 0..31 (row group)
    const int lc = (tid & 7) * 4;     // 0,4,...,28 (k offset)

    const int warp = tid >> 5;
    const int lane = tid & 31;
    const int grp  = lane >> 2;
    const int q    = lane & 3;
    const int wm   = (warp & 3) * 32;   // warp M base within tile
    const int wn   = (warp >> 2) * 64;  // warp N base within tile

    float acc[2][8][4];
    #pragma unroll
    for (int i = 0; i < 2; i++)
        #pragma unroll
        for (int j = 0; j < 8; j++)
            #pragma unroll
            for (int v = 0; v < 4; v++) acc[i][j][v] = 0.f;

    for (int k0 = 0; k0 < Ktot; k0 += BK) {
        // ---- load A tile (tf32-rounded) ----
        #pragma unroll
        for (int i = 0; i < 4; i++) {
            const int row  = lr + i * 32;
            const int grow = bm + row;
            const float* p;
            if (MODE == 0) {
                if (k0 < PX)
                    p = x + (size_t)grow * PX + k0 + lc;
                else
                    p = h_prev + ((size_t)lz * B_SZ + grow) * PH + (k0 - PX) + lc;
            } else if (MODE == 1) {
                p = g_hidden + (size_t)grow * HID + (layer - 1) * PH + k0 + lc;
            } else {
                p = g_hidden + (size_t)grow * HID + k0 + lc;
            }
            float4 v = *(const float4*)p;
            As[row][lc + 0] = f2tf32(v.x);
            As[row][lc + 1] = f2tf32(v.y);
            As[row][lc + 2] = f2tf32(v.z);
            As[row][lc + 3] = f2tf32(v.w);
        }
        // ---- load B tile (weight rows, K-major) ----
        #pragma unroll
        for (int i = 0; i < 4; i++) {
            const int row = lr + i * 32;
            const int gn  = bn + row;
            const float* p;
            if (MODE == 0) {
                p = Wg + ((size_t)lz * NG + gn) * IN_DIM + k0 + lc;
            } else if (MODE == 1) {
                p = Wg + ((size_t)layer * NG + gn) * IN_DIM + (PX + PH) + k0 + lc;
            } else {
                p = (gn < PVT) ? (W_y + (size_t)gn * HID + k0 + lc)
                               : (W_E + (size_t)(gn - PVT) * HID + k0 + lc);
            }
            float4 v = *(const float4*)p;
            Bs[row][lc + 0] = f2tf32(v.x);
            Bs[row][lc + 1] = f2tf32(v.y);
            Bs[row][lc + 2] = f2tf32(v.z);
            Bs[row][lc + 3] = f2tf32(v.w);
        }
        __syncthreads();

        // ---- MMA over BK in k8 steps ----
        #pragma unroll
        for (int kk = 0; kk < BK; kk += 8) {
            uint32_t a[2][4];
            #pragma unroll
            for (int im = 0; im < 2; im++) {
                const int r = wm + im * 16 + grp;
                a[im][0] = __float_as_uint(As[r    ][kk + q    ]);
                a[im][1] = __float_as_uint(As[r + 8][kk + q    ]);
                a[im][2] = __float_as_uint(As[r    ][kk + q + 4]);
                a[im][3] = __float_as_uint(As[r + 8][kk + q + 4]);
            }
            #pragma unroll
            for (int jn = 0; jn < 8; jn++) {
                const int n = wn + jn * 8 + grp;
                const uint32_t b0 = __float_as_uint(Bs[n][kk + q    ]);
                const uint32_t b1 = __float_as_uint(Bs[n][kk + q + 4]);
                mma_tf32(acc[0][jn], a[0], b0, b1);
                mma_tf32(acc[1][jn], a[1], b0, b1);
            }
        }
        __syncthreads();
    }

    // ---- epilogue ----
    #pragma unroll
    for (int im = 0; im < 2; im++) {
        const int r0 = bm + wm + im * 16 + grp;   // rows r0, r0+8
        #pragma unroll
        for (int jn = 0; jn < 8; jn++) {
            const int c0 = bn + wn + jn * 8 + 2 * q;  // cols c0, c0+1
            #pragma unroll
            for (int v = 0; v < 4; v++) {
                const int r = r0 + ((v >> 1) ? 8 : 0);
                const int c = c0 + (v & 1);
                float val = acc[im][jn][v];
                if (MODE == 0) {
                    val += bg[(size_t)lz * NG + c];
                    g_Gp[((size_t)lz * B_SZ + r) * NG + c] = val;
                } else if (MODE == 1) {
                    float* d = &g_Gp[((size_t)layer * B_SZ + r) * NG + c];
                    *d = val + *d;
                } else {
                    if (c < PVT) {
                        d_out[(size_t)r * PVT + c] = val + b_y[c];
                    } else {
                        d_out[(size_t)B_SZ * PVT + (size_t)r * PET + (c - PVT)]
                            = val + b_E[c - PVT];
                    }
                }
            }
        }
    }
}

__global__ void lstm_pointwise(const float* __restrict__ c_prev, int layer) {
    const int idx = blockIdx.x * blockDim.x + threadIdx.x;
    const int b = idx >> 10;        // / PH
    const int h = idx & (PH - 1);
    const float* Gb = g_Gp + ((size_t)layer * B_SZ + b) * NG;
    const float gi = Gb[h];
    const float gf = Gb[PH + h];
    const float go = Gb[2 * PH + h];
    const float gs = Gb[3 * PH + h];
    const float ig = 1.f / (1.f + __expf(-gi));
    const float fg = 1.f / (1.f + __expf(-gf));
    const float og = 1.f / (1.f + __expf(-go));
    const float sg = tanhf(gs);
    const float cp = c_prev[((size_t)layer * B_SZ + b) * PH + h];
    const float c  = fg * cp + ig * sg;
    const float hn = og * tanhf(c);
    g_hidden[(size_t)b * HID + layer * PH + h] = hn;
}

extern "C" void kernel_launch(void* const* d_in, const int* in_sizes, int n_in,
                              void* d_out, int out_size) {
    const float* x      = (const float*)d_in[0];
    const float* h_prev = (const float*)d_in[1];
    const float* c_prev = (const float*)d_in[2];
    const float* Wg     = (const float*)d_in[3];
    const float* bg     = (const float*)d_in[4];
    const float* W_y    = (const float*)d_in[5];
    const float* b_y    = (const float*)d_in[6];
    const float* W_E    = (const float*)d_in[7];
    const float* b_E    = (const float*)d_in[8];
    float* out = (float*)d_out;

    const dim3 blk(256);
    // 1) parallel partial gates for all 4 layers (K = 1536, includes bias)
    gemm_tf32<0><<<dim3(NG / 128, B_SZ / 128, PL), blk>>>(
        x, h_prev, Wg, bg, W_y, b_y, W_E, b_E, out, 0);
    // 2) layer 0: prev_layer is zero -> gates already complete
    lstm_pointwise<<<(B_SZ * PH) / 256, 256>>>(c_prev, 0);
    // 3) layers 1..3: add prev-layer tail GEMM (K = 1024), then pointwise
    for (int l = 1; l < PL; l++) {
        gemm_tf32<1><<<dim3(NG / 128, B_SZ / 128, 1), blk>>>(
            x, h_prev, Wg, bg, W_y, b_y, W_E, b_E, out, l);
        lstm_pointwise<<<(B_SZ * PH) / 256, 256>>>(c_prev, l);
    }
    // 4) fused heads: [512 x 4096] x [4096 x (512+256)]
    gemm_tf32<2><<<dim3((PVT + PET) / 128, B_SZ / 128, 1), blk>>>(
        x, h_prev, Wg, bg, W_y, b_y, W_E, b_E, out, 0);
}

// round 2
// speedup vs baseline: 1.9050x; 1.9050x over previous
#include <cuda_runtime.h>
#include <cstdint>

#define B_SZ   512
#define PX     512
#define PH     1024
#define PL     4
#define PVT    512
#define PET    256
#define NG     4096      // 4 gates * PH
#define HID    4096      // PL * PH
#define IN_DIM 2560

#define BM 128
#define BN 128
#define BK 16
#define RS 20            // smem row stride in floats (conflict-free: 20*r mod 32 distinct for r=0..7)

// Scratch (no allocations allowed)
__device__ float g_Gp[PL * B_SZ * NG];      // gate pre-activations
__device__ float g_hidden[B_SZ * HID];      // concat hidden

__device__ __forceinline__ uint32_t cvt_tf32(float x) {
    uint32_t r;
    asm("cvt.rna.tf32.f32 %0, %1;" : "=r"(r) : "f"(x));
    return r;
}

__device__ __forceinline__ void cp16(uint32_t dst, const void* src) {
    asm volatile("cp.async.cg.shared.global [%0], [%1], 16;" :: "r"(dst), "l"(src));
}

__device__ __forceinline__ void mma_tf32(float (&d)[4], const uint32_t (&a)[4],
                                         uint32_t b0, uint32_t b1) {
    asm volatile(
        "mma.sync.aligned.m16n8k8.row.col.f32.tf32.tf32.f32 "
        "{%0,%1,%2,%3}, {%4,%5,%6,%7}, {%8,%9}, {%0,%1,%2,%3};\n"
        : "+f"(d[0]), "+f"(d[1]), "+f"(d[2]), "+f"(d[3])
        : "r"(a[0]), "r"(a[1]), "r"(a[2]), "r"(a[3]), "r"(b0), "r"(b1));
}

// MODE 0: partial gates, all layers in parallel (grid.z = layer), K=1536
// MODE 1: sequential prev-layer tail for `layer`, K=1024, accumulate into g_Gp
// MODE 2: fused heads, K=4096, split output layout
template<int MODE>
__global__ void __launch_bounds__(256, 2)
gemm_tf32(const float* __restrict__ x,
          const float* __restrict__ h_prev,
          const float* __restrict__ Wg,
          const float* __restrict__ bg,
          const float* __restrict__ W_y, const float* __restrict__ b_y,
          const float* __restrict__ W_E, const float* __restrict__ b_E,
          float* __restrict__ d_out,
          int layer)
{
    __shared__ float As[2][BM * RS];
    __shared__ float Bs[2][BN * RS];

    const int tid = threadIdx.x;
    const int bm  = blockIdx.y * BM;
    const int bn  = blockIdx.x * BN;
    const int lz  = (MODE == 0) ? blockIdx.z : layer;

    int Ktot;
    if (MODE == 0)      Ktot = PX + PH;   // 1536
    else if (MODE == 1) Ktot = PH;        // 1024
    else                Ktot = HID;       // 4096
    const int nK = Ktot / BK;

    // loader mapping: thread -> (row = tid/2, k-window = (tid&1)*8), 2x 16B chunks each tile
    const int lrow = tid >> 1;
    const int lkw  = (tid & 1) * 8;
    const uint32_t sA0 = (uint32_t)__cvta_generic_to_shared(&As[0][0]);
    const uint32_t sA1 = (uint32_t)__cvta_generic_to_shared(&As[1][0]);
    const uint32_t sB0 = (uint32_t)__cvta_generic_to_shared(&Bs[0][0]);
    const uint32_t sB1 = (uint32_t)__cvta_generic_to_shared(&Bs[1][0]);
    const uint32_t offAB = (uint32_t)(lrow * RS + lkw) * 4u;

    const int warp = tid >> 5;
    const int lane = tid & 31;
    const int grp  = lane >> 2;
    const int q    = lane & 3;
    const int wm   = (warp & 3) * 32;
    const int wn   = (warp >> 2) * 64;

    float acc[2][8][4];
    #pragma unroll
    for (int i = 0; i < 2; i++)
        #pragma unroll
        for (int j = 0; j < 8; j++)
            #pragma unroll
            for (int v = 0; v < 4; v++) acc[i][j][v] = 0.f;

    // ---- stage loader ----
    auto load_stage = [&](int buf, int k0) {
        const int gk = k0 + lkw;
        // A chunk
        const float* pa;
        if (MODE == 0) {
            pa = (gk < PX)
               ? x + (size_t)(bm + lrow) * PX + gk
               : h_prev + ((size_t)lz * B_SZ + bm + lrow) * PH + (gk - PX);
        } else if (MODE == 1) {
            pa = g_hidden + (size_t)(bm + lrow) * HID + (layer - 1) * PH + gk;
        } else {
            pa = g_hidden + (size_t)(bm + lrow) * HID + gk;
        }
        const uint32_t da = (buf ? sA1 : sA0) + offAB;
        cp16(da, pa);
        cp16(da + 16, pa + 4);
        // B chunk
        const float* pb;
        if (MODE == 0) {
            pb = Wg + ((size_t)lz * NG + bn + lrow) * IN_DIM + gk;
        } else if (MODE == 1) {
            pb = Wg + ((size_t)layer * NG + bn + lrow) * IN_DIM + (PX + PH) + gk;
        } else {
            pb = (bn + lrow < PVT)
               ? W_y + (size_t)(bn + lrow) * HID + gk
               : W_E + (size_t)(bn + lrow - PVT) * HID + gk;
        }
        const uint32_t db = (buf ? sB1 : sB0) + offAB;
        cp16(db, pb);
        cp16(db + 16, pb + 4);
    };

    // prologue: stage 0 in flight
    load_stage(0, 0);
    asm volatile("cp.async.commit_group;");

    for (int s = 0; s < nK; s++) {
        const int buf = s & 1;
        if (s + 1 < nK) {
            load_stage(buf ^ 1, (s + 1) * BK);
            asm volatile("cp.async.commit_group;");
            asm volatile("cp.async.wait_group 1;");
        } else {
            asm volatile("cp.async.wait_group 0;");
        }
        __syncthreads();

        const float* __restrict__ Ab = As[buf];
        const float* __restrict__ Bb = Bs[buf];
        #pragma unroll
        for (int kk = 0; kk < BK; kk += 8) {
            uint32_t a[2][4];
            #pragma unroll
            for (int im = 0; im < 2; im++) {
                const int r = wm + im * 16 + grp;
                a[im][0] = cvt_tf32(Ab[(r    ) * RS + kk + q    ]);
                a[im][1] = cvt_tf32(Ab[(r + 8) * RS + kk + q    ]);
                a[im][2] = cvt_tf32(Ab[(r    ) * RS + kk + q + 4]);
                a[im][3] = cvt_tf32(Ab[(r + 8) * RS + kk + q + 4]);
            }
            #pragma unroll
            for (int jn = 0; jn < 8; jn++) {
                const int n = wn + jn * 8 + grp;
                const uint32_t b0 = cvt_tf32(Bb[n * RS + kk + q    ]);
                const uint32_t b1 = cvt_tf32(Bb[n * RS + kk + q + 4]);
                mma_tf32(acc[0][jn], a[0], b0, b1);
                mma_tf32(acc[1][jn], a[1], b0, b1);
            }
        }
        __syncthreads();
    }

    // ---- epilogue (float2 stores; c0 always even) ----
    #pragma unroll
    for (int im = 0; im < 2; im++) {
        const int r0 = bm + wm + im * 16 + grp;
        #pragma unroll
        for (int jn = 0; jn < 8; jn++) {
            const int c0 = bn + wn + jn * 8 + 2 * q;
            const float2 lo = make_float2(acc[im][jn][0], acc[im][jn][1]);
            const float2 hi = make_float2(acc[im][jn][2], acc[im][jn][3]);
            if (MODE == 0) {
                const float2 b2 = *(const float2*)&bg[(size_t)lz * NG + c0];
                float2* d0 = (float2*)&g_Gp[((size_t)lz * B_SZ + r0    ) * NG + c0];
                float2* d1 = (float2*)&g_Gp[((size_t)lz * B_SZ + r0 + 8) * NG + c0];
                *d0 = make_float2(lo.x + b2.x, lo.y + b2.y);
                *d1 = make_float2(hi.x + b2.x, hi.y + b2.y);
            } else if (MODE == 1) {
                float2* d0 = (float2*)&g_Gp[((size_t)layer * B_SZ + r0    ) * NG + c0];
                float2* d1 = (float2*)&g_Gp[((size_t)layer * B_SZ + r0 + 8) * NG + c0];
                const float2 o0 = *d0, o1 = *d1;
                *d0 = make_float2(lo.x + o0.x, lo.y + o0.y);
                *d1 = make_float2(hi.x + o1.x, hi.y + o1.y);
            } else {
                if (c0 < PVT) {
                    const float2 b2 = *(const float2*)&b_y[c0];
                    float2* d0 = (float2*)&d_out[(size_t)(r0    ) * PVT + c0];
                    float2* d1 = (float2*)&d_out[(size_t)(r0 + 8) * PVT + c0];
                    *d0 = make_float2(lo.x + b2.x, lo.y + b2.y);
                    *d1 = make_float2(hi.x + b2.x, hi.y + b2.y);
                } else {
                    const int c = c0 - PVT;
                    const float2 b2 = *(const float2*)&b_E[c];
                    float* base = d_out + (size_t)B_SZ * PVT;
                    float2* d0 = (float2*)&base[(size_t)(r0    ) * PET + c];
                    float2* d1 = (float2*)&base[(size_t)(r0 + 8) * PET + c];
                    *d0 = make_float2(lo.x + b2.x, lo.y + b2.y);
                    *d1 = make_float2(hi.x + b2.x, hi.y + b2.y);
                }
            }
        }
    }
}

__global__ void lstm_pointwise(const float* __restrict__ c_prev, int layer) {
    const int idx = (blockIdx.x * blockDim.x + threadIdx.x) * 4;
    const int b = idx >> 10;
    const int h = idx & (PH - 1);
    const float* Gb = g_Gp + ((size_t)layer * B_SZ + b) * NG;
    const float4 gi = *(const float4*)&Gb[h];
    const float4 gf = *(const float4*)&Gb[PH + h];
    const float4 go = *(const float4*)&Gb[2 * PH + h];
    const float4 gs = *(const float4*)&Gb[3 * PH + h];
    const float4 cp = *(const float4*)&c_prev[((size_t)layer * B_SZ + b) * PH + h];
    float4 out;
    {
        const float ig = 1.f / (1.f + __expf(-gi.x));
        const float fg = 1.f / (1.f + __expf(-gf.x));
        const float og = 1.f / (1.f + __expf(-go.x));
        const float c  = fg * cp.x + ig * tanhf(gs.x);
        out.x = og * tanhf(c);
    }
    {
        const float ig = 1.f / (1.f + __expf(-gi.y));
        const float fg = 1.f / (1.f + __expf(-gf.y));
        const float og = 1.f / (1.f + __expf(-go.y));
        const float c  = fg * cp.y + ig * tanhf(gs.y);
        out.y = og * tanhf(c);
    }
    {
        const float ig = 1.f / (1.f + __expf(-gi.z));
        const float fg = 1.f / (1.f + __expf(-gf.z));
        const float og = 1.f / (1.f + __expf(-go.z));
        const float c  = fg * cp.z + ig * tanhf(gs.z);
        out.z = og * tanhf(c);
    }
    {
        const float ig = 1.f / (1.f + __expf(-gi.w));
        const float fg = 1.f / (1.f + __expf(-gf.w));
        const float og = 1.f / (1.f + __expf(-go.w));
        const float c  = fg * cp.w + ig * tanhf(gs.w);
        out.w = og * tanhf(c);
    }
    *(float4*)&g_hidden[(size_t)b * HID + layer * PH + h] = out;
}

extern "C" void kernel_launch(void* const* d_in, const int* in_sizes, int n_in,
                              void* d_out, int out_size) {
    const float* x      = (const float*)d_in[0];
    const float* h_prev = (const float*)d_in[1];
    const float* c_prev = (const float*)d_in[2];
    const float* Wg     = (const float*)d_in[3];
    const float* bg     = (const float*)d_in[4];
    const float* W_y    = (const float*)d_in[5];
    const float* b_y    = (const float*)d_in[6];
    const float* W_E    = (const float*)d_in[7];
    const float* b_E    = (const float*)d_in[8];
    float* out = (float*)d_out;

    const dim3 blk(256);
    // 1) parallel partial gates for all 4 layers (K=1536, includes bias)
    gemm_tf32<0><<<dim3(NG / BN, B_SZ / BM, PL), blk>>>(
        x, h_prev, Wg, bg, W_y, b_y, W_E, b_E, out, 0);
    // 2) layer 0: prev_layer is zero -> gates complete
    lstm_pointwise<<<(B_SZ * PH) / 1024, 256>>>(c_prev, 0);
    // 3) layers 1..3: prev-layer tail GEMM (K=1024) + pointwise
    for (int l = 1; l < PL; l++) {
        gemm_tf32<1><<<dim3(NG / BN, B_SZ / BM, 1), blk>>>(
            x, h_prev, Wg, bg, W_y, b_y, W_E, b_E, out, l);
        lstm_pointwise<<<(B_SZ * PH) / 1024, 256>>>(c_prev, l);
    }
    // 4) fused heads: [512 x 4096] x [4096 x 768]
    gemm_tf32<2><<<dim3((PVT + PET) / BN, B_SZ / BM, 1), blk>>>(
        x, h_prev, Wg, bg, W_y, b_y, W_E, b_E, out, 0);
}